// round 1
// baseline (speedup 1.0000x reference)
#include <cuda_runtime.h>
#include <cuda_bf16.h>
#include <cstdint>

// Problem constants
#define NQ      16384      // B*H*W
#define NEG     4096       // embeddings per group
#define GR      4
#define KD      64         // embedding dim
#define TQ      128        // queries per block
#define TE      128        // embeddings per smem tile

typedef unsigned long long ull;

// ---- device scratch (static, no allocation) ----
__device__ int   g_idx[NQ * GR];           // argmax indices (int)
__device__ float g_embn[NEG * GR * KD];    // normalized embedding
__device__ int   g_hist[NEG];              // histogram of idx[:, 3]

// ---- f32x2 helpers ----
__device__ __forceinline__ void ffma2(ull& d, ull a, ull b) {
    asm("fma.rn.f32x2 %0, %1, %2, %0;" : "+l"(d) : "l"(a), "l"(b));
}
__device__ __forceinline__ float2 unpack2(ull v) {
    float2 r;
    asm("mov.b64 {%0, %1}, %2;" : "=f"(r.x), "=f"(r.y) : "l"(v));
    return r;
}

// ============================================================================
// Main: fused GEMM (z . e^T per group) + row argmax.
// z layout: (16, 256, 32, 32) -> z[n,g,c] = z[b*262144 + (g*64+c)*1024 + hw],
//   n = b*1024 + hw. 128 consecutive n stay within one b.
// Dyn smem: zs_dup[64][256] (z dup'd into f32x2 pairs) | es[64][128] | best.
// ============================================================================
__global__ __launch_bounds__(256, 2)
void vq_argmax_kernel(const float* __restrict__ z,
                      const float* __restrict__ emb,
                      float* __restrict__ out_idx)
{
    extern __shared__ float smem[];
    float* zs   = smem;                    // 64 * 256 floats (dup'd)
    float* es   = smem + 64 * 256;         // 64 * 128 floats
    float* bval = es + 64 * 128;           // 128
    int*   bidx = (int*)(bval + TQ);       // 128

    const int g     = blockIdx.y;
    const int qbase = blockIdx.x * TQ;
    const int tid   = threadIdx.x;

    // ---- load z tile (duplicated for f32x2 'a' operand) ----
    {
        const int b   = qbase >> 10;
        const int hwb = qbase & 1023;
        const float* zb = z + (size_t)b * 262144 + (size_t)(g * 64) * 1024 + hwb;
        #pragma unroll
        for (int i = 0; i < 8; i++) {
            int idx = tid + i * 256;       // 0..2047 float4 chunks
            int k   = idx >> 5;            // 32 float4 per k-row
            int q4  = (idx & 31) * 4;
            float4 v = *reinterpret_cast<const float4*>(zb + k * 1024 + q4);
            float4 d0 = make_float4(v.x, v.x, v.y, v.y);
            float4 d1 = make_float4(v.z, v.z, v.w, v.w);
            *reinterpret_cast<float4*>(zs + (k << 8) + q4 * 2)     = d0;
            *reinterpret_cast<float4*>(zs + (k << 8) + q4 * 2 + 4) = d1;
        }
    }
    if (tid < TQ) { bval[tid] = -3.0e38f; bidx[tid] = 0; }

    const int ty = tid >> 4;   // 0..15 -> owns q rows ty*8..ty*8+7
    const int tx = tid & 15;   // 0..15 -> owns e cols tx*8..tx*8+7
    const float* eg = emb + (size_t)g * NEG * KD;

    for (int et = 0; et < NEG / TE; et++) {
        __syncthreads();   // zs ready (iter 0) / es free from previous compute
        // ---- load+transpose e tile: es[k][e] ----
        {
            int e  = tid >> 1;
            int kh = (tid & 1) * 32;
            const float* erow = eg + (size_t)(et * TE + e) * KD + kh;
            #pragma unroll
            for (int j4 = 0; j4 < 8; j4++) {
                float4 v = *reinterpret_cast<const float4*>(erow + j4 * 4);
                int kb = kh + j4 * 4;
                es[(kb + 0) * TE + e] = v.x;
                es[(kb + 1) * TE + e] = v.y;
                es[(kb + 2) * TE + e] = v.z;
                es[(kb + 3) * TE + e] = v.w;
            }
        }
        __syncthreads();

        // ---- 8q x 8e register tile, f32x2 FMA over K=64 ----
        ull acc[8][4];
        #pragma unroll
        for (int i = 0; i < 8; i++)
            #pragma unroll
            for (int j = 0; j < 4; j++) acc[i][j] = 0ull;

        #pragma unroll 4
        for (int k = 0; k < KD; k++) {
            const ulonglong2* ap =
                reinterpret_cast<const ulonglong2*>(zs + (k << 8) + (ty << 4));
            ulonglong2 A0 = ap[0], A1 = ap[1], A2 = ap[2], A3 = ap[3];
            const ulonglong2* bp =
                reinterpret_cast<const ulonglong2*>(es + (k << 7) + (tx << 3));
            ulonglong2 B0 = bp[0], B1 = bp[1];
            ull av[8] = {A0.x, A0.y, A1.x, A1.y, A2.x, A2.y, A3.x, A3.y};
            ull bv[4] = {B0.x, B0.y, B1.x, B1.y};
            #pragma unroll
            for (int i = 0; i < 8; i++) {
                ffma2(acc[i][0], av[i], bv[0]);
                ffma2(acc[i][1], av[i], bv[1]);
                ffma2(acc[i][2], av[i], bv[2]);
                ffma2(acc[i][3], av[i], bv[3]);
            }
        }

        // ---- argmax epilogue (first-occurrence tie-break) ----
        #pragma unroll
        for (int i = 0; i < 8; i++) {
            float bv = -3.0e38f; int bi = 0;
            #pragma unroll
            for (int j = 0; j < 4; j++) {
                float2 p = unpack2(acc[i][j]);
                int e0 = et * TE + tx * 8 + j * 2;
                if (p.x > bv) { bv = p.x; bi = e0; }
                if (p.y > bv) { bv = p.y; bi = e0 + 1; }
            }
            #pragma unroll
            for (int m = 8; m >= 1; m >>= 1) {
                float ov = __shfl_xor_sync(0xffffffffu, bv, m, 16);
                int   oi = __shfl_xor_sync(0xffffffffu, bi, m, 16);
                if (ov > bv || (ov == bv && oi < bi)) { bv = ov; bi = oi; }
            }
            if (tx == 0) {
                int q = ty * 8 + i;
                if (bv > bval[q]) { bval[q] = bv; bidx[q] = bi; }
            }
        }
    }
    __syncthreads();
    if (tid < TQ) {
        int n = qbase + tid;
        int v = bidx[tid];
        g_idx[n * GR + g] = v;
        out_idx[n * GR + g] = (float)v;
    }
}

// ============================================================================
// Normalize embedding rows (one warp per row)
// ============================================================================
__global__ void embnorm_kernel(const float* __restrict__ emb)
{
    int warp = (blockIdx.x * blockDim.x + threadIdx.x) >> 5;
    int lane = threadIdx.x & 31;
    if (warp >= NEG * GR) return;
    float2 v = reinterpret_cast<const float2*>(emb + (size_t)warp * KD)[lane];
    float s = v.x * v.x + v.y * v.y;
    #pragma unroll
    for (int m = 16; m >= 1; m >>= 1) s += __shfl_xor_sync(0xffffffffu, s, m);
    float inv = 1.0f / fmaxf(sqrtf(s), 1e-12f);
    float2 o = make_float2(v.x * inv, v.y * inv);
    reinterpret_cast<float2*>(g_embn + (size_t)warp * KD)[lane] = o;
}

// ============================================================================
// quant: out[b, g*64+c, h, w] = embn[g*4096 + idx[n,g], c]   (coalesced writes)
// ============================================================================
__global__ void quant_kernel(float* __restrict__ out)
{
    int o = blockIdx.x * blockDim.x + threadIdx.x;
    if (o >= 16 * 256 * 1024) return;
    int hw = o & 1023;
    int ch = (o >> 10) & 255;
    int b  = o >> 18;
    int gg = ch >> 6, c = ch & 63;
    int n  = (b << 10) + hw;
    int v  = g_idx[n * GR + gg];
    out[o] = g_embn[((size_t)((gg << 12) + v)) * KD + c];
}

__global__ void zhist_kernel()
{
    int i = blockIdx.x * blockDim.x + threadIdx.x;
    if (i < NEG) g_hist[i] = 0;
}

// one-hot of idx[:, 3] + histogram
__global__ void scatter_kernel(float* __restrict__ out_me)
{
    int n = blockIdx.x * blockDim.x + threadIdx.x;
    if (n >= NQ) return;
    int v = g_idx[n * GR + 3];
    out_me[(size_t)n * NEG + v] = 1.0f;
    atomicAdd(&g_hist[v], 1);
}

__global__ void perp_kernel(float* __restrict__ out_p)
{
    __shared__ float red[32];
    int t = threadIdx.x;
    float s = 0.0f;
    for (int i = t; i < NEG; i += 1024) {
        float p = (float)g_hist[i] * (1.0f / 16384.0f);
        s += p * logf(p + 1e-10f);
    }
    #pragma unroll
    for (int m = 16; m >= 1; m >>= 1) s += __shfl_xor_sync(0xffffffffu, s, m);
    if ((t & 31) == 0) red[t >> 5] = s;
    __syncthreads();
    if (t < 32) {
        float x = red[t];
        #pragma unroll
        for (int m = 16; m >= 1; m >>= 1) x += __shfl_xor_sync(0xffffffffu, x, m);
        if (t == 0) out_p[0] = expf(-x);
    }
}

// ============================================================================
// Output layout (fp32, concatenated, 71,368,717 elements):
//   [0, 4194304)        quant
//   [4194304, +12)      vq_loss(4) commit_loss(4) codebook_usage(4)  = zeros
//   [4194316]           perplexity
//   [4194317, +16384*4096)  min_encodings
//   [71303181, +65536)  idx (cast to float)
// ============================================================================
extern "C" void kernel_launch(void* const* d_in, const int* in_sizes, int n_in,
                              void* d_out, int out_size)
{
    const float* z   = (const float*)d_in[0];
    const float* emb = (const float*)d_in[1];
    float* out = (float*)d_out;

    const size_t QUANT   = (size_t)16 * 256 * 1024;          // 4194304
    const size_t PERP    = QUANT + 12;
    const size_t ME_OFF  = QUANT + 13;
    const size_t ME_SZ   = (size_t)NQ * NEG;                  // 67108864
    const size_t IDX_OFF = ME_OFF + ME_SZ;                    // 71303181

    static_assert(TQ * 8 == 1024 || true, "");

    const int SMEM = (64 * 256 + 64 * 128 + TQ) * 4 + TQ * 4; // 99328 B
    cudaFuncSetAttribute(vq_argmax_kernel,
                         cudaFuncAttributeMaxDynamicSharedMemorySize, SMEM);

    // zero losses + perplexity slot + min_encodings (268 MB)
    cudaMemsetAsync(out + QUANT, 0, (13 + ME_SZ) * sizeof(float));

    embnorm_kernel<<<2048, 256>>>(emb);
    zhist_kernel<<<16, 256>>>();

    dim3 agrid(NQ / TQ, GR);   // (128, 4)
    vq_argmax_kernel<<<agrid, 256, SMEM>>>(z, emb, out + IDX_OFF);

    quant_kernel<<<16384, 256>>>(out);
    scatter_kernel<<<64, 256>>>(out + ME_OFF);
    perp_kernel<<<1, 1024>>>(out + PERP);
}

// round 2
// speedup vs baseline: 1.8275x; 1.8275x over previous
#include <cuda_runtime.h>
#include <cuda_bf16.h>
#include <cstdint>

// Problem constants
#define NQ      16384      // B*H*W
#define NEG     4096       // embeddings per group
#define GR      4
#define KD      64         // embedding dim
#define TQ      128        // queries per block
#define CAP     64         // candidate capacity per row

// ---- device scratch (static, no allocation) ----
__device__ int      g_idx[NQ * GR];              // final argmax indices
__device__ float    g_embn[NEG * GR * KD];       // normalized embedding (fp32)
__device__ int      g_embqT[GR * 32 * 16 * 128]; // int8-packed, tile-transposed
__device__ int      g_hist[NEG];                 // histogram of idx[:, 3]
__device__ int      g_cnt[NQ * GR];              // candidate counts
__device__ int      g_cand[NQ * GR * CAP];       // candidate lists
__device__ unsigned g_zmax_bits;                 // max |z| as float bits
__device__ float    g_sz;                        // z quant scale
__device__ int      g_margin;                    // int-domain margin

// ============================================================================
// init: zero counters / hist / zmax
// ============================================================================
__global__ void init_kernel()
{
    int i = blockIdx.x * 256 + threadIdx.x;
    if (i < NQ * GR) g_cnt[i] = 0;
    if (i < NEG)     g_hist[i] = 0;
    if (i == 0)      g_zmax_bits = 0u;
}

// ============================================================================
// max |z| reduction (z has 4,194,304 floats = 1,048,576 float4)
// ============================================================================
__global__ void zmax_kernel(const float* __restrict__ z)
{
    unsigned m = 0u;
    int stride = gridDim.x * blockDim.x;
    for (int i = blockIdx.x * blockDim.x + threadIdx.x; i < 1048576; i += stride) {
        float4 v = reinterpret_cast<const float4*>(z)[i];
        m = max(m, __float_as_uint(fabsf(v.x)));
        m = max(m, __float_as_uint(fabsf(v.y)));
        m = max(m, __float_as_uint(fabsf(v.z)));
        m = max(m, __float_as_uint(fabsf(v.w)));
    }
    m = __reduce_max_sync(0xffffffffu, m);
    if ((threadIdx.x & 31) == 0) atomicMax(&g_zmax_bits, m);
}

__global__ void finalize_kernel()
{
    float zm = fmaxf(__uint_as_float(g_zmax_bits), 1e-12f);
    float sz = 126.0f / zm;
    g_sz = sz;
    g_margin = (int)(0.25f * sz * 126.0f) + 2;
}

// ============================================================================
// emb prep: normalize rows -> g_embn ; quantize+pack+transpose -> g_embqT
// one warp per embedding row
// ============================================================================
__global__ void embprep_kernel(const float* __restrict__ emb)
{
    int warp = (blockIdx.x * blockDim.x + threadIdx.x) >> 5;
    int lane = threadIdx.x & 31;
    if (warp >= NEG * GR) return;
    float2 v = reinterpret_cast<const float2*>(emb + (size_t)warp * KD)[lane];
    float s = v.x * v.x + v.y * v.y;
    #pragma unroll
    for (int m = 16; m >= 1; m >>= 1) s += __shfl_xor_sync(0xffffffffu, s, m);
    float inv = 1.0f / fmaxf(sqrtf(s), 1e-12f);
    float2 o = make_float2(v.x * inv, v.y * inv);
    reinterpret_cast<float2*>(g_embn + (size_t)warp * KD)[lane] = o;

    // int8 quantize (|coord| <= 1 -> scale 126 is overflow-safe)
    int q0 = __float2int_rn(o.x * 126.0f);
    int q1 = __float2int_rn(o.y * 126.0f);
    int half = (q0 & 0xFF) | ((q1 & 0xFF) << 8);
    // word for k4 = lane (<16): bytes = coords 4*k4 .. 4*k4+3 from lanes 2k4, 2k4+1
    int lo = __shfl_sync(0xffffffffu, half, (lane & 15) * 2);
    int hi = __shfl_sync(0xffffffffu, half, (lane & 15) * 2 + 1);
    if (lane < 16) {
        int word = (lo & 0xFFFF) | (hi << 16);
        int g  = warp >> 12;
        int el = warp & 4095;
        int et = el >> 7, ec = el & 127;
        g_embqT[(((size_t)(g * 32 + et)) * 16 + lane) * 128 + ec] = word;
    }
}

// ============================================================================
// Prefilter: int8 dp4a GEMM + streaming running-max + margin candidate push.
// z layout: z[n,g,c] = z[b*262144 + (g*64+c)*1024 + hw], n = b*1024+hw.
// ============================================================================
__global__ __launch_bounds__(256, 2)
void prefilter_kernel(const float* __restrict__ z)
{
    __shared__ int zs[16 * 128];   // [k4][q] packed int8 z
    __shared__ int es[16 * 128];   // [k4][e] packed int8 emb tile

    const int g     = blockIdx.y;
    const int qbase = blockIdx.x * TQ;
    const int tid   = threadIdx.x;
    const float sz  = g_sz;
    const int  marg = g_margin;

    // ---- load + quantize z tile ----
    {
        const int b   = qbase >> 10;
        const int hwb = qbase & 1023;
        const float* zb = z + (size_t)b * 262144 + (size_t)(g * 64) * 1024 + hwb;
        #pragma unroll
        for (int w = 0; w < 8; w++) {
            int idx = tid + w * 256;        // 0..2047
            int k4  = idx >> 7;
            int q   = idx & 127;
            int word = 0;
            #pragma unroll
            for (int bi = 0; bi < 4; bi++) {
                float v = zb[(k4 * 4 + bi) * 1024 + q];
                int qv = __float2int_rn(v * sz);
                word |= (qv & 0xFF) << (bi * 8);
            }
            zs[idx] = word;
        }
    }

    const int ty = tid >> 4;   // 0..15 -> q rows ty*8..+7
    const int tx = tid & 15;   // 0..15 -> e cols tx*8..+7

    int rm[8];
    #pragma unroll
    for (int i = 0; i < 8; i++) rm[i] = (int)0x80000000;

    const int4* esrc = reinterpret_cast<const int4*>(g_embqT + (size_t)g * 32 * 2048);

    for (int et = 0; et < 32; et++) {
        __syncthreads();
        {
            const int4* s4 = esrc + et * 512;
            int4* d4 = reinterpret_cast<int4*>(es);
            d4[tid]       = s4[tid];
            d4[tid + 256] = s4[tid + 256];
        }
        __syncthreads();

        int acc[8][8];
        #pragma unroll
        for (int i = 0; i < 8; i++)
            #pragma unroll
            for (int j = 0; j < 8; j++) acc[i][j] = 0;

        #pragma unroll 4
        for (int k4 = 0; k4 < 16; k4++) {
            int a[8], bb[8];
            #pragma unroll
            for (int i = 0; i < 8; i++) a[i] = zs[k4 * 128 + ty * 8 + i];
            #pragma unroll
            for (int j = 0; j < 8; j++) bb[j] = es[k4 * 128 + tx * 8 + j];
            #pragma unroll
            for (int i = 0; i < 8; i++)
                #pragma unroll
                for (int j = 0; j < 8; j++)
                    acc[i][j] = __dp4a(a[i], bb[j], acc[i][j]);
        }

        // ---- running max + margin candidate collection ----
        #pragma unroll
        for (int i = 0; i < 8; i++) {
            int m = acc[i][0];
            #pragma unroll
            for (int j = 1; j < 8; j++) m = max(m, acc[i][j]);
            #pragma unroll
            for (int o = 8; o >= 1; o >>= 1)
                m = max(m, __shfl_xor_sync(0xffffffffu, m, o, 16));
            rm[i] = max(rm[i], m);
            int thr  = rm[i] - marg;
            int rowg = (qbase + ty * 8 + i) * GR + g;
            #pragma unroll
            for (int j = 0; j < 8; j++) {
                if (acc[i][j] >= thr) {
                    int slot = atomicAdd(&g_cnt[rowg], 1);
                    if (slot < CAP)
                        g_cand[(size_t)rowg * CAP + slot] = et * 128 + tx * 8 + j;
                }
            }
        }
    }
}

// ============================================================================
// Rescore: exact fp32 dot over candidates, first-index tie-break.
// Block: 256 threads, 8 consecutive n (one b), 32 rows; warp does 4 rows.
// ============================================================================
__global__ __launch_bounds__(256)
void rescore_kernel(const float* __restrict__ z, float* __restrict__ out_idx)
{
    __shared__ float zsh[256 * 9];   // [c][hwi] with pad stride 9

    const int tid = threadIdx.x;
    const int n0  = blockIdx.x * 8;
    const int b   = n0 >> 10;
    const int hw0 = n0 & 1023;
    const float* zb = z + (size_t)b * 262144 + hw0;

    #pragma unroll
    for (int w = 0; w < 8; w++) {
        int idx = tid + w * 256;        // 2048 = 256 c * 8 hw
        int c = idx >> 3, hwi = idx & 7;
        zsh[c * 9 + hwi] = zb[(size_t)c * 1024 + hwi];
    }
    __syncthreads();

    const int wid = tid >> 5, lane = tid & 31;
    for (int rr = 0; rr < 4; rr++) {
        int lr  = wid * 4 + rr;          // 0..31
        int hwi = lr >> 2;
        int g   = lr & 3;
        int n   = n0 + hwi;
        int row = n * GR + g;
        int cnt = g_cnt[row];
        if (cnt > CAP) cnt = CAP;

        float bv = -3.0e38f;
        int   be = 0x7FFFFFFF;
        for (int base = 0; base < cnt; base += 32) {
            int c = base + lane;
            if (c < cnt) {
                int e = g_cand[(size_t)row * CAP + c];
                const float4* er = reinterpret_cast<const float4*>(
                    g_embn + ((size_t)(g * NEG + e)) * KD);
                const float* zr = zsh + (g * 64) * 9 + hwi;
                float acc = 0.0f;
                #pragma unroll
                for (int kk = 0; kk < 16; kk++) {
                    float4 ev = er[kk];
                    acc = fmaf(zr[(kk * 4 + 0) * 9], ev.x, acc);
                    acc = fmaf(zr[(kk * 4 + 1) * 9], ev.y, acc);
                    acc = fmaf(zr[(kk * 4 + 2) * 9], ev.z, acc);
                    acc = fmaf(zr[(kk * 4 + 3) * 9], ev.w, acc);
                }
                if (acc > bv || (acc == bv && e < be)) { bv = acc; be = e; }
            }
        }
        // cross-lane argmax: sortable key + redux
        unsigned u = __float_as_uint(bv);
        u = ((int)u < 0) ? ~u : (u | 0x80000000u);
        unsigned m = __reduce_max_sync(0xffffffffu, u);
        unsigned bidm = (u == m) ? (unsigned)be : 0xFFFFFFFFu;
        unsigned bi = __reduce_min_sync(0xffffffffu, bidm);
        if (lane == 0) {
            g_idx[row] = (int)bi;
            out_idx[row] = (float)bi;
        }
    }
}

// ============================================================================
// quant: out[b, g*64+c, h, w] = embn[g*4096 + idx[n,g], c]
// ============================================================================
__global__ void quant_kernel(float* __restrict__ out)
{
    int o = blockIdx.x * blockDim.x + threadIdx.x;
    if (o >= 16 * 256 * 1024) return;
    int hw = o & 1023;
    int ch = (o >> 10) & 255;
    int b  = o >> 18;
    int gg = ch >> 6, c = ch & 63;
    int n  = (b << 10) + hw;
    int v  = g_idx[n * GR + gg];
    out[o] = g_embn[((size_t)((gg << 12) + v)) * KD + c];
}

// one-hot of idx[:, 3] + histogram
__global__ void scatter_kernel(float* __restrict__ out_me)
{
    int n = blockIdx.x * blockDim.x + threadIdx.x;
    if (n >= NQ) return;
    int v = g_idx[n * GR + 3];
    out_me[(size_t)n * NEG + v] = 1.0f;
    atomicAdd(&g_hist[v], 1);
}

__global__ void perp_kernel(float* __restrict__ out_p)
{
    __shared__ float red[32];
    int t = threadIdx.x;
    float s = 0.0f;
    for (int i = t; i < NEG; i += 1024) {
        float p = (float)g_hist[i] * (1.0f / 16384.0f);
        s += p * logf(p + 1e-10f);
    }
    #pragma unroll
    for (int m = 16; m >= 1; m >>= 1) s += __shfl_xor_sync(0xffffffffu, s, m);
    if ((t & 31) == 0) red[t >> 5] = s;
    __syncthreads();
    if (t < 32) {
        float x = red[t];
        #pragma unroll
        for (int m = 16; m >= 1; m >>= 1) x += __shfl_xor_sync(0xffffffffu, x, m);
        if (t == 0) out_p[0] = expf(-x);
    }
}

// ============================================================================
// Output layout (fp32, concatenated, 71,368,717 elements):
//   [0, 4194304)            quant
//   [4194304, +12)          vq_loss(4) commit_loss(4) codebook_usage(4) = zeros
//   [4194316]               perplexity
//   [4194317, +16384*4096)  min_encodings
//   [71303181, +65536)      idx (cast to float)
// ============================================================================
extern "C" void kernel_launch(void* const* d_in, const int* in_sizes, int n_in,
                              void* d_out, int out_size)
{
    const float* z   = (const float*)d_in[0];
    const float* emb = (const float*)d_in[1];
    float* out = (float*)d_out;

    const size_t QUANT   = (size_t)16 * 256 * 1024;          // 4194304
    const size_t PERP    = QUANT + 12;
    const size_t ME_OFF  = QUANT + 13;
    const size_t ME_SZ   = (size_t)NQ * NEG;                  // 67108864
    const size_t IDX_OFF = ME_OFF + ME_SZ;                    // 71303181

    // zero losses + perplexity slot + min_encodings (268 MB)
    cudaMemsetAsync(out + QUANT, 0, (13 + ME_SZ) * sizeof(float));

    init_kernel<<<256, 256>>>();
    zmax_kernel<<<1024, 256>>>(z);
    finalize_kernel<<<1, 1>>>();
    embprep_kernel<<<2048, 256>>>(emb);

    dim3 agrid(NQ / TQ, GR);   // (128, 4)
    prefilter_kernel<<<agrid, 256>>>(z);

    rescore_kernel<<<NQ / 8, 256>>>(z, out + IDX_OFF);

    quant_kernel<<<16384, 256>>>(out);
    scatter_kernel<<<64, 256>>>(out + ME_OFF);
    perp_kernel<<<1, 1024>>>(out + PERP);
}

// round 4
// speedup vs baseline: 2.4507x; 1.3410x over previous
#include <cuda_runtime.h>
#include <cuda_fp16.h>
#include <cstdint>

// Problem constants
#define NQ      16384      // B*H*W
#define NEG     4096       // embeddings per group
#define GR      4
#define KD      64         // embedding dim
#define TQ      128        // queries per block
#define NT      128        // e per tile
#define NTILES  (NEG / NT) // 32
#define CAP     64         // candidate capacity per row

typedef unsigned long long ull;

// ---- device scratch (static, no allocation) ----
__device__ int      g_idx[NQ * GR];               // final argmax indices
__device__ float    g_embn[NEG * GR * KD];        // normalized embedding (fp32)
__device__ int      g_embh[GR * NTILES * 4096];   // fp16 swizzled 16KB tile images
__device__ int      g_hist[NEG];                  // histogram of idx[:, 3]
__device__ int      g_cnt[NQ * GR];               // candidate counts
__device__ int      g_cand[NQ * GR * CAP];        // candidate lists

// ============================================================================
// PTX helpers (base-target: ldmatrix sm_75+, mma.sync sm_80+)
// ============================================================================
__device__ __forceinline__ uint32_t smem_u32(const void* p) {
    uint32_t a;
    asm("{ .reg .u64 t; cvta.to.shared.u64 t, %1; cvt.u32.u64 %0, t; }"
        : "=r"(a) : "l"(p));
    return a;
}
#define LDSM_X4(r, addr) \
    asm volatile("ldmatrix.sync.aligned.m8n8.x4.shared.b16 {%0,%1,%2,%3}, [%4];" \
        : "=r"((r)[0]), "=r"((r)[1]), "=r"((r)[2]), "=r"((r)[3]) : "r"(addr))

__device__ __forceinline__ void mma16816(float* c, const uint32_t* a,
                                         const uint32_t* b) {
    asm volatile("mma.sync.aligned.m16n8k16.row.col.f32.f16.f16.f32 "
        "{%0,%1,%2,%3}, {%4,%5,%6,%7}, {%8,%9}, {%0,%1,%2,%3};"
        : "+f"(c[0]), "+f"(c[1]), "+f"(c[2]), "+f"(c[3])
        : "r"(a[0]), "r"(a[1]), "r"(a[2]), "r"(a[3]), "r"(b[0]), "r"(b[1]));
}

// ============================================================================
// init: zero counters / histogram
// ============================================================================
__global__ void init_kernel()
{
    int i = blockIdx.x * 256 + threadIdx.x;
    if (i < NQ * GR) g_cnt[i] = 0;
    if (i < NEG)     g_hist[i] = 0;
}

// ============================================================================
// emb prep: normalize rows -> g_embn(fp32); fp16 XOR-swizzled tile images.
// Tile image: 128 e-rows x 64 k halfs; uint idx = er*32 + ((kblk^ (er&7))<<2)
//   + half-pair, kblk = k/8. One warp per embedding row.
// ============================================================================
__global__ void embprep_kernel(const float* __restrict__ emb)
{
    int warp = (blockIdx.x * blockDim.x + threadIdx.x) >> 5;
    int lane = threadIdx.x & 31;
    if (warp >= NEG * GR) return;
    float2 v = reinterpret_cast<const float2*>(emb + (size_t)warp * KD)[lane];
    float s = v.x * v.x + v.y * v.y;
    #pragma unroll
    for (int m = 16; m >= 1; m >>= 1) s += __shfl_xor_sync(0xffffffffu, s, m);
    float inv = 1.0f / fmaxf(sqrtf(s), 1e-12f);
    float2 o = make_float2(v.x * inv, v.y * inv);
    reinterpret_cast<float2*>(g_embn + (size_t)warp * KD)[lane] = o;

    __half2 h2 = __floats2half2_rn(o.x, o.y);
    int w; memcpy(&w, &h2, 4);
    int g  = warp >> 12;
    int el = warp & 4095;
    int et = el >> 7, er = el & 127;
    // coords c = 2*lane, 2*lane+1 ; kblk = lane>>2 ; pair-in-block = lane&3
    int ui = er * 32 + ((((lane >> 2)) ^ (er & 7)) << 2) + (lane & 3);
    g_embh[(size_t)(g * NTILES + et) * 4096 + ui] = w;
}

// ============================================================================
// Tensor-core argmax via mma.sync m16n8k16 (fp16 in, fp32 accum) + streaming
// margin candidate filter. z[n,g,c] = z[b*262144 + (g*64+c)*1024 + hw].
// Grid (128, 4), 256 threads, 2 CTAs/SM.
// Dyn smem: [0,512) margins | A 16KB @1024 | B0 @17408 | B1 @33792.
// ============================================================================
__global__ __launch_bounds__(256, 2)
void vq_mma_kernel(const float* __restrict__ z)
{
    extern __shared__ __align__(1024) char smem[];
    float* smarg = reinterpret_cast<float*>(smem);
    uint32_t sbase = smem_u32(smem);
    const uint32_t aA = sbase + 1024;
    const uint32_t aB[2] = { sbase + 17408, sbase + 33792 };
    int4* sB4[2] = { reinterpret_cast<int4*>(smem + 17408),
                     reinterpret_cast<int4*>(smem + 33792) };

    const int tid   = threadIdx.x;
    const int g     = blockIdx.y;
    const int qbase = blockIdx.x * TQ;

    // ---- build A tile (fp16, swizzled) + per-row norm ----
    {
        const int b   = qbase >> 10;
        const int hwb = qbase & 1023;
        const float* zb = z + (size_t)b * 262144 + (size_t)(g * 64) * 1024 + hwb;
        const int q  = tid & 127;
        const int ph = tid >> 7;                 // handles c-pairs ph*16..+15
        __half2* A2 = reinterpret_cast<__half2*>(smem + 1024);
        float n2 = 0.0f;
        #pragma unroll
        for (int i = 0; i < 16; i++) {
            int c = (ph * 16 + i) * 2;
            float v0 = zb[(size_t)c * 1024 + q];
            float v1 = zb[(size_t)(c + 1) * 1024 + q];
            n2 += v0 * v0 + v1 * v1;
            int ui = q * 32 + (((c >> 3) ^ (q & 7)) << 2) + ((c & 7) >> 1);
            A2[ui] = __floats2half2_rn(v0, v1);
        }
        if (ph == 0) smarg[q] = n2;
        // ---- preload B(0) ----
        {
            const int4* s4 = reinterpret_cast<const int4*>(
                g_embh + (size_t)g * NTILES * 4096);
            #pragma unroll
            for (int i = 0; i < 4; i++) sB4[0][tid + i * 256] = s4[tid + i * 256];
        }
        __syncthreads();
        if (ph == 1) smarg[q] = 0.006f * sqrtf(smarg[q] + n2);
        __syncthreads();
    }

    const int w  = tid >> 5;
    const int l  = tid & 31;
    const int qw = (w & 3) * 32;
    const int ew = (w >> 2) * 64;

    float rm[4], marg[4];
    int   rowg[4];
    #pragma unroll
    for (int qb = 0; qb < 2; qb++)
        #pragma unroll
        for (int h = 0; h < 2; h++) {
            int slot = qb * 2 + h;
            int rq = qw + qb * 16 + (l >> 2) + h * 8;
            rm[slot]   = -3.0e38f;
            marg[slot] = smarg[rq];
            rowg[slot] = (qbase + rq) * GR + g;
        }

    const int4* esrc = reinterpret_cast<const int4*>(
        g_embh + (size_t)g * NTILES * 4096);

    for (int t = 0; t < NTILES; t++) {
        // prefetch next B tile into the other buffer
        if (t + 1 < NTILES) {
            const int4* s4 = esrc + (size_t)(t + 1) * 1024;
            int4* d4 = sB4[(t + 1) & 1];
            #pragma unroll
            for (int i = 0; i < 4; i++) d4[tid + i * 256] = s4[tid + i * 256];
        }

        float acc[2][8][4];
        #pragma unroll
        for (int qb = 0; qb < 2; qb++)
            #pragma unroll
            for (int eb = 0; eb < 8; eb++)
                #pragma unroll
                for (int j = 0; j < 4; j++) acc[qb][eb][j] = 0.0f;

        const uint32_t base = aB[t & 1];
        #pragma unroll
        for (int ks = 0; ks < 4; ks++) {
            uint32_t RA[2][4];
            #pragma unroll
            for (int qb = 0; qb < 2; qb++) {
                int row = qw + qb * 16 + (l & 15);
                int blk = ks * 2 + (l >> 4);
                LDSM_X4(RA[qb], aA + row * 128 + ((blk ^ (row & 7)) << 4));
            }
            uint32_t RB[4][4];
            #pragma unroll
            for (int ebp = 0; ebp < 4; ebp++) {
                int row = ew + ebp * 16 + (l & 7) + ((l >> 4) << 3);
                int blk = ks * 2 + ((l >> 3) & 1);
                LDSM_X4(RB[ebp], base + row * 128 + ((blk ^ (row & 7)) << 4));
            }
            #pragma unroll
            for (int qb = 0; qb < 2; qb++)
                #pragma unroll
                for (int eb = 0; eb < 8; eb++)
                    mma16816(acc[qb][eb], RA[qb], &RB[eb >> 1][(eb & 1) * 2]);
        }

        // ---- streaming argmax epilogue ----
        #pragma unroll
        for (int qb = 0; qb < 2; qb++)
            #pragma unroll
            for (int h = 0; h < 2; h++) {
                const int slot = qb * 2 + h;
                float mx = -3.0e38f;
                #pragma unroll
                for (int eb = 0; eb < 8; eb++) {
                    mx = fmaxf(mx, acc[qb][eb][h * 2]);
                    mx = fmaxf(mx, acc[qb][eb][h * 2 + 1]);
                }
                mx = fmaxf(mx, __shfl_xor_sync(0xffffffffu, mx, 1));
                mx = fmaxf(mx, __shfl_xor_sync(0xffffffffu, mx, 2));
                if (mx > rm[slot]) rm[slot] = mx;
                const float thr = rm[slot] - marg[slot];
                #pragma unroll
                for (int eb = 0; eb < 8; eb++) {
                    #pragma unroll
                    for (int j = 0; j < 2; j++) {
                        float vv = acc[qb][eb][h * 2 + j];
                        if (vv >= thr) {
                            int sc = atomicAdd(&g_cnt[rowg[slot]], 1);
                            if (sc < CAP)
                                g_cand[(size_t)rowg[slot] * CAP + sc] =
                                    t * NT + ew + eb * 8 + (l & 3) * 2 + j;
                        }
                    }
                }
            }
        __syncthreads();
    }
}

// ============================================================================
// Rescore: exact fp32 dot over candidates, first-index tie-break.
// Block: 256 threads, 8 consecutive n (one b), 32 rows; warp does 4 rows.
// ============================================================================
__global__ __launch_bounds__(256)
void rescore_kernel(const float* __restrict__ z, float* __restrict__ out_idx)
{
    __shared__ float zsh[256 * 9];   // [c][hwi] pad stride 9

    const int tid = threadIdx.x;
    const int n0  = blockIdx.x * 8;
    const int b   = n0 >> 10;
    const int hw0 = n0 & 1023;
    const float* zb = z + (size_t)b * 262144 + hw0;

    #pragma unroll
    for (int w = 0; w < 8; w++) {
        int idx = tid + w * 256;
        int c = idx >> 3, hwi = idx & 7;
        zsh[c * 9 + hwi] = zb[(size_t)c * 1024 + hwi];
    }
    __syncthreads();

    const int wid = tid >> 5, lane = tid & 31;
    for (int rr = 0; rr < 4; rr++) {
        int lr  = wid * 4 + rr;
        int hwi = lr >> 2;
        int g   = lr & 3;
        int n   = n0 + hwi;
        int row = n * GR + g;
        int cnt = g_cnt[row];
        if (cnt > CAP) cnt = CAP;

        float bv = -3.0e38f;
        int   be = 0x7FFFFFFF;
        for (int base = 0; base < cnt; base += 32) {
            int c = base + lane;
            if (c < cnt) {
                int e = g_cand[(size_t)row * CAP + c];
                const float4* er = reinterpret_cast<const float4*>(
                    g_embn + ((size_t)(g * NEG + e)) * KD);
                const float* zr = zsh + (g * 64) * 9 + hwi;
                float acc = 0.0f;
                #pragma unroll
                for (int kk = 0; kk < 16; kk++) {
                    float4 ev = er[kk];
                    acc = fmaf(zr[(kk * 4 + 0) * 9], ev.x, acc);
                    acc = fmaf(zr[(kk * 4 + 1) * 9], ev.y, acc);
                    acc = fmaf(zr[(kk * 4 + 2) * 9], ev.z, acc);
                    acc = fmaf(zr[(kk * 4 + 3) * 9], ev.w, acc);
                }
                if (acc > bv || (acc == bv && e < be)) { bv = acc; be = e; }
            }
        }
        unsigned u = __float_as_uint(bv);
        u = ((int)u < 0) ? ~u : (u | 0x80000000u);
        unsigned m = __reduce_max_sync(0xffffffffu, u);
        unsigned bidm = (u == m) ? (unsigned)be : 0xFFFFFFFFu;
        unsigned bi = __reduce_min_sync(0xffffffffu, bidm);
        if (lane == 0) {
            g_idx[row] = (int)bi;
            out_idx[row] = (float)bi;
        }
    }
}

// ============================================================================
// quant: out[b, g*64+c, h, w] = embn[g*4096 + idx[n,g], c]
// ============================================================================
__global__ void quant_kernel(float* __restrict__ out)
{
    int o = blockIdx.x * blockDim.x + threadIdx.x;
    if (o >= 16 * 256 * 1024) return;
    int hw = o & 1023;
    int ch = (o >> 10) & 255;
    int b  = o >> 18;
    int gg = ch >> 6, c = ch & 63;
    int n  = (b << 10) + hw;
    int v  = g_idx[n * GR + gg];
    out[o] = g_embn[((size_t)((gg << 12) + v)) * KD + c];
}

// one-hot of idx[:, 3] + histogram
__global__ void scatter_kernel(float* __restrict__ out_me)
{
    int n = blockIdx.x * blockDim.x + threadIdx.x;
    if (n >= NQ) return;
    int v = g_idx[n * GR + 3];
    out_me[(size_t)n * NEG + v] = 1.0f;
    atomicAdd(&g_hist[v], 1);
}

__global__ void perp_kernel(float* __restrict__ out_p)
{
    __shared__ float red[32];
    int t = threadIdx.x;
    float s = 0.0f;
    for (int i = t; i < NEG; i += 1024) {
        float p = (float)g_hist[i] * (1.0f / 16384.0f);
        s += p * logf(p + 1e-10f);
    }
    #pragma unroll
    for (int m = 16; m >= 1; m >>= 1) s += __shfl_xor_sync(0xffffffffu, s, m);
    if ((t & 31) == 0) red[t >> 5] = s;
    __syncthreads();
    if (t < 32) {
        float x = red[t];
        #pragma unroll
        for (int m = 16; m >= 1; m >>= 1) x += __shfl_xor_sync(0xffffffffu, x, m);
        if (t == 0) out_p[0] = expf(-x);
    }
}

// ============================================================================
// Output layout (fp32, concatenated, 71,368,717 elements):
//   [0, 4194304)            quant
//   [4194304, +12)          vq_loss(4) commit_loss(4) codebook_usage(4) = zeros
//   [4194316]               perplexity
//   [4194317, +16384*4096)  min_encodings
//   [71303181, +65536)      idx (cast to float)
// ============================================================================
extern "C" void kernel_launch(void* const* d_in, const int* in_sizes, int n_in,
                              void* d_out, int out_size)
{
    const float* z   = (const float*)d_in[0];
    const float* emb = (const float*)d_in[1];
    float* out = (float*)d_out;

    const size_t QUANT   = (size_t)16 * 256 * 1024;          // 4194304
    const size_t PERP    = QUANT + 12;
    const size_t ME_OFF  = QUANT + 13;
    const size_t ME_SZ   = (size_t)NQ * NEG;                  // 67108864
    const size_t IDX_OFF = ME_OFF + ME_SZ;                    // 71303181

    const int SMEM = 50176;   // margins + A 16KB + 2x16KB B
    cudaFuncSetAttribute(vq_mma_kernel,
                         cudaFuncAttributeMaxDynamicSharedMemorySize, SMEM);

    // zero losses + perplexity slot + min_encodings (268 MB)
    cudaMemsetAsync(out + QUANT, 0, (13 + ME_SZ) * sizeof(float));

    init_kernel<<<256, 256>>>();
    embprep_kernel<<<2048, 256>>>(emb);

    dim3 agrid(NQ / TQ, GR);   // (128, 4)
    vq_mma_kernel<<<agrid, 256, SMEM>>>(z);

    rescore_kernel<<<NQ / 8, 256>>>(z, out + IDX_OFF);

    quant_kernel<<<16384, 256>>>(out);
    scatter_kernel<<<64, 256>>>(out + ME_OFF);
    perp_kernel<<<1, 1024>>>(out + PERP);
}